// round 6
// baseline (speedup 1.0000x reference)
#include <cuda_runtime.h>

#define HH 512
#define WW 512
#define BB 2
#define GRID 256
#define NTHR 512

// Packed row-pass result, one uint16 per pixel:
//   bit15 = mask (1 = fg), bits[0:15) = row distance to nearest OPPOSITE-class
//   pixel (0x7fff sentinel = none in this row). 1 MB, L2-resident.
__device__ unsigned short g_pack16[BB * HH * WW];

// Grid barrier state (replay-safe: count returns to 0, gen monotonically
// increases across graph replays; no per-launch reset needed).
__device__ unsigned int g_bar_count;
__device__ volatile unsigned int g_bar_gen;

// ---------------------------------------------------------------------------
// Fused SDF kernel.
// Phase 1 (rows): 4 rows per block via 512-bit bitmask + ffs/clz word scans.
// Grid barrier (all 256 blocks are co-resident: launch_bounds(512,2) ->
//   >= 2 blocks/SM on 148 SMs = 296 >= 256, so the spin cannot deadlock).
// Phase 2 (cols): exact adaptive-window min-plus (stop when r^2 >= best),
//   opposite plane only, 2 px/thread per uint32 __ldcg, coalesced across
//   threads, 2 row-works per thread. Fused sqrt epilogue.
// ---------------------------------------------------------------------------
__global__ void __launch_bounds__(NTHR, 2)
sdf_fused(const float* __restrict__ gt, float* __restrict__ out) {
    const int x = threadIdx.x;
    const int bid = blockIdx.x;

    __shared__ unsigned int sw[4][WW / 32];   // 4 row masks

    // ---------------- Phase 1: row pass (rows 4*bid .. 4*bid+3) -----------
    float v[4];
    #pragma unroll
    for (int k = 0; k < 4; ++k)
        v[k] = gt[(size_t)(bid * 4 + k) * WW + x];

    unsigned int m[4];
    #pragma unroll
    for (int k = 0; k < 4; ++k) {
        m[k] = (v[k] == 1.0f) ? 1u : 0u;
        const unsigned int bits = __ballot_sync(0xFFFFFFFFu, m[k] != 0u);
        if ((x & 31) == 0) sw[k][x >> 5] = bits;
    }
    __syncthreads();

    const int w0 = x >> 5, off = x & 31;
    #pragma unroll
    for (int k = 0; k < 4; ++k) {
        const unsigned int xorm = m[k] ? 0xFFFFFFFFu : 0u;
        const unsigned int cur = sw[k][w0] ^ xorm;

        int right = 0x7fff;
        {
            const unsigned int hi = cur & (0xFFFFFFFEu << off);
            if (hi) {
                right = (__ffs(hi) - 1) - off;
            } else {
                #pragma unroll 1
                for (int w = w0 + 1; w < WW / 32; ++w) {
                    const unsigned int t = sw[k][w] ^ xorm;
                    if (t) { right = (w << 5) + (__ffs(t) - 1) - x; break; }
                }
            }
        }
        int left = 0x7fff;
        {
            const unsigned int lo = cur & ((1u << off) - 1u);
            if (lo) {
                left = off - (31 - __clz(lo));
            } else {
                #pragma unroll 1
                for (int w = w0 - 1; w >= 0; --w) {
                    const unsigned int t = sw[k][w] ^ xorm;
                    if (t) { left = x - ((w << 5) + (31 - __clz(t))); break; }
                }
            }
        }

        const unsigned int d = (unsigned int)min(min(left, right), 0x7fff);
        g_pack16[(size_t)(bid * 4 + k) * WW + x] =
            (unsigned short)(d | (m[k] << 15));
    }

    // ---------------- Grid barrier ----------------------------------------
    __syncthreads();
    if (x == 0) {
        __threadfence();                       // publish g_pack16 writes
        const unsigned int old_gen = g_bar_gen;
        const unsigned int t = atomicAdd(&g_bar_count, 1u);
        if (t == GRID - 1) {
            g_bar_count = 0;                   // reset for next replay
            __threadfence();
            atomicAdd((unsigned int*)&g_bar_gen, 1u);
        } else {
            while (g_bar_gen == old_gen) { }
        }
    }
    __syncthreads();

    // ---------------- Phase 2: column pass --------------------------------
    const int pair = x & 255;                  // uint32 pixel-pair index
    const int sub = x >> 8;                    // 0/1
    const unsigned int* __restrict__ pk =
        reinterpret_cast<const unsigned int*>(g_pack16);

    #pragma unroll 1
    for (int k = 0; k < 2; ++k) {
        const int w = bid * 4 + sub * 2 + k;   // w = b*512 + i, in [0, 1024)
        const int i = w & 511;
        const unsigned int* __restrict__ col =
            pk + (size_t)(w - i) * (WW / 2) + pair;   // (w - i) = b*512

        const unsigned int u = __ldcg(&col[i * (WW / 2)]);
        const unsigned int mA = (u >> 15) & 1u;
        const unsigned int mB = (u >> 31) & 1u;
        const int roA = (int)(u & 0x7fffu);
        const int roB = (int)((u >> 16) & 0x7fffu);
        float bestA = (float)(roA * roA);
        float bestB = (float)(roB * roB);

        #pragma unroll 1
        for (int r = 1; r < HH; ++r) {
            const float rr = (float)(r * r);
            if (rr >= bestA && rr >= bestB) break;
            const int up = i - r, dn = i + r;
            if (up >= 0) {
                const unsigned int q = __ldcg(&col[up * (WW / 2)]);
                const int ra = (int)(q & 0x7fffu), rb = (int)((q >> 16) & 0x7fffu);
                const float fa = (((q >> 15) & 1u) != mA) ? 0.0f : (float)(ra * ra);
                const float fb = (((q >> 31) & 1u) != mB) ? 0.0f : (float)(rb * rb);
                bestA = fminf(bestA, fa + rr);
                bestB = fminf(bestB, fb + rr);
            }
            if (dn < HH) {
                const unsigned int q = __ldcg(&col[dn * (WW / 2)]);
                const int ra = (int)(q & 0x7fffu), rb = (int)((q >> 16) & 0x7fffu);
                const float fa = (((q >> 15) & 1u) != mA) ? 0.0f : (float)(ra * ra);
                const float fb = (((q >> 31) & 1u) != mB) ? 0.0f : (float)(rb * rb);
                bestA = fminf(bestA, fa + rr);
                bestB = fminf(bestB, fb + rr);
            }
        }

        float2 o;
        o.x = (mA ? -1.0f : 1.0f) * sqrtf(bestA);
        o.y = (mB ? -1.0f : 1.0f) * sqrtf(bestB);
        reinterpret_cast<float2*>(out)[(size_t)w * (WW / 2) + pair] = o;
    }
}

extern "C" void kernel_launch(void* const* d_in, const int* in_sizes, int n_in,
                              void* d_out, int out_size) {
    const float* gt = (const float*)d_in[0];
    float* out = (float*)d_out;
    (void)in_sizes; (void)n_in; (void)out_size;

    sdf_fused<<<GRID, NTHR>>>(gt, out);
}